// round 1
// baseline (speedup 1.0000x reference)
#include <cuda_runtime.h>
#include <math.h>

// Shapes fixed by the problem: x[8,2048,1024] fp32, prototypes[64,1024] fp32,
// attn_mask[8,2048] int32 (unused for the computation).
#define DDIM 1024
#define NEXP 64
#define SEQ  2048
#define TM   128
#define KC   64
#define NT   256
#define MAXTOK 16384

// Scratch (allocation-free rule: __device__ globals)
__device__ float g_logits[MAXTOK * NEXP];   // normalized per-token logits
__device__ float g_inorm[MAXTOK];           // 1 / max(||x_t||, 1e-8)

// ---------------------------------------------------------------------------
// Kernel 0: per-token inverse L2 norm. One warp per token, fixed-order reduce.
// ---------------------------------------------------------------------------
__global__ void norm_kernel(const float* __restrict__ x, int ntok) {
    int warp = (blockIdx.x * blockDim.x + threadIdx.x) >> 5;
    int lane = threadIdx.x & 31;
    if (warp >= ntok) return;
    const float4* row = reinterpret_cast<const float4*>(x + (size_t)warp * DDIM);
    float s = 0.f;
#pragma unroll
    for (int j = 0; j < DDIM / 128; j++) {
        float4 v = row[lane + 32 * j];
        s += v.x * v.x + v.y * v.y + v.z * v.z + v.w * v.w;
    }
#pragma unroll
    for (int off = 16; off; off >>= 1)
        s += __shfl_xor_sync(0xffffffffu, s, off);
    if (lane == 0)
        g_inorm[warp] = 1.0f / fmaxf(sqrtf(s), 1e-8f);
}

// ---------------------------------------------------------------------------
// Kernel 1: fp32 GEMM  L[t,e] = (x_t . p_e) * inorm[t]
// Tile: TM=128 tokens x NEXP=64 experts, K chunks of 64. 256 threads,
// per-thread 4x8 register tile. Deterministic (fixed reduction order).
// ---------------------------------------------------------------------------
__global__ __launch_bounds__(NT) void gemm_kernel(const float* __restrict__ x,
                                                  const float* __restrict__ proto) {
    __shared__ float Asm[TM][KC + 4];     // [128][68] — pad for a-load banks + f4 align
    __shared__ float Psm[KC][NEXP + 4];   // [64][68]  — transposed, f4-aligned b reads

    const int t  = threadIdx.x;
    const int tx = t & 7;    // expert group: experts tx*8 .. tx*8+7
    const int ty = t >> 3;   // row group: tokens ty*4 .. ty*4+3
    const size_t blockRow = (size_t)blockIdx.x * TM;

    float acc[4][8];
#pragma unroll
    for (int i = 0; i < 4; i++)
#pragma unroll
        for (int j = 0; j < 8; j++) acc[i][j] = 0.f;

    for (int kc = 0; kc < DDIM; kc += KC) {
        // Load A tile: 128 rows x 64 cols, 8 float4 per thread, coalesced.
#pragma unroll
        for (int i = 0; i < 8; i++) {
            int f   = t + i * NT;           // 0..2047
            int row = f >> 4;
            int col = (f & 15) << 2;
            float4 v = *reinterpret_cast<const float4*>(
                x + (blockRow + row) * DDIM + kc + col);
            *reinterpret_cast<float4*>(&Asm[row][col]) = v;
        }
        // Load P tile transposed: Psm[k][expert]. 4 float4 per thread.
#pragma unroll
        for (int i = 0; i < 4; i++) {
            int f   = t + i * NT;           // 0..1023
            int e   = f >> 4;               // expert 0..63
            int col = (f & 15) << 2;        // k-local 0..60
            float4 v = *reinterpret_cast<const float4*>(
                proto + (size_t)e * DDIM + kc + col);
            Psm[col + 0][e] = v.x;
            Psm[col + 1][e] = v.y;
            Psm[col + 2][e] = v.z;
            Psm[col + 3][e] = v.w;
        }
        __syncthreads();

#pragma unroll 16
        for (int k = 0; k < KC; k++) {
            float a[4];
#pragma unroll
            for (int i = 0; i < 4; i++) a[i] = Asm[ty * 4 + i][k];
            float4 b0 = *reinterpret_cast<const float4*>(&Psm[k][tx * 8]);
            float4 b1 = *reinterpret_cast<const float4*>(&Psm[k][tx * 8 + 4]);
            float b[8] = {b0.x, b0.y, b0.z, b0.w, b1.x, b1.y, b1.z, b1.w};
#pragma unroll
            for (int i = 0; i < 4; i++)
#pragma unroll
                for (int j = 0; j < 8; j++)
                    acc[i][j] = fmaf(a[i], b[j], acc[i][j]);
        }
        __syncthreads();
    }

    // Epilogue: scale by 1/||x|| and store normalized logits.
#pragma unroll
    for (int i = 0; i < 4; i++) {
        size_t row = blockRow + ty * 4 + i;
        float rn = g_inorm[row];
        float4 o0 = make_float4(acc[i][0] * rn, acc[i][1] * rn,
                                acc[i][2] * rn, acc[i][3] * rn);
        float4 o1 = make_float4(acc[i][4] * rn, acc[i][5] * rn,
                                acc[i][6] * rn, acc[i][7] * rn);
        *reinterpret_cast<float4*>(&g_logits[row * NEXP + tx * 8])     = o0;
        *reinterpret_cast<float4*>(&g_logits[row * NEXP + tx * 8 + 4]) = o1;
    }
}

// ---------------------------------------------------------------------------
// Kernel 2: window-3 average of logits (left-replicate token 0), top-2 with
// JAX tie-break (lower index wins), renormalized weights. One warp per token.
// ---------------------------------------------------------------------------
__device__ __forceinline__ bool better(float v, int vi, float w, int wi) {
    return (v > w) || (v == w && vi < wi);
}

__global__ void topk_kernel(float* __restrict__ out, int ntok, int out_size) {
    int warp = (blockIdx.x * blockDim.x + threadIdx.x) >> 5;
    int lane = threadIdx.x & 31;
    if (warp >= ntok) return;

    int b = warp / SEQ;
    int s = warp - b * SEQ;
    size_t t0 = (size_t)warp;
    size_t t1 = (size_t)b * SEQ + (s >= 1 ? s - 1 : 0);
    size_t t2 = (size_t)b * SEQ + (s >= 2 ? s - 2 : 0);

    float v0 = (g_logits[t0 * NEXP + lane] + g_logits[t1 * NEXP + lane] +
                g_logits[t2 * NEXP + lane]) / 3.0f;
    float v1 = (g_logits[t0 * NEXP + lane + 32] + g_logits[t1 * NEXP + lane + 32] +
                g_logits[t2 * NEXP + lane + 32]) / 3.0f;

    // local sorted pair (tie -> lower index = lane)
    float a1, a2; int i1, i2;
    if (v0 >= v1) { a1 = v0; i1 = lane;      a2 = v1; i2 = lane + 32; }
    else          { a1 = v1; i1 = lane + 32; a2 = v0; i2 = lane;      }

    // butterfly merge of sorted pairs — all lanes converge to global top-2
#pragma unroll
    for (int off = 16; off; off >>= 1) {
        float ob1 = __shfl_xor_sync(0xffffffffu, a1, off);
        int   oj1 = __shfl_xor_sync(0xffffffffu, i1, off);
        float ob2 = __shfl_xor_sync(0xffffffffu, a2, off);
        int   oj2 = __shfl_xor_sync(0xffffffffu, i2, off);
        bool aw = better(a1, i1, ob1, oj1);
        float n1  = aw ? a1 : ob1;  int ni1 = aw ? i1 : oj1;
        float c   = aw ? ob1 : a1;  int ci  = aw ? oj1 : i1;  // loser of top1
        float d   = aw ? a2 : ob2;  int di  = aw ? i2 : oj2;  // winner's 2nd
        bool cw = better(c, ci, d, di);
        a1 = n1; i1 = ni1;
        a2 = cw ? c : d; i2 = cw ? ci : di;
    }

    if (lane == 0) {
        // renormalized top-2 softmax weights: w1 = 1/(1+e^{l2-l1})
        float e2 = expf(a2 - a1);
        float inv = 1.0f / (1.0f + e2);
        float w1 = inv;
        float w2 = e2 * inv;
        // output layout: modules [ntok,2] then weights [ntok,2], as float32
        if (out_size >= 4 * ntok) {
            out[t0 * 2 + 0] = (float)i1;
            out[t0 * 2 + 1] = (float)i2;
            out[(size_t)ntok * 2 + t0 * 2 + 0] = w1;
            out[(size_t)ntok * 2 + t0 * 2 + 1] = w2;
        } else if (out_size >= 2 * ntok) {
            // fallback if harness only materializes the first return value
            out[t0 * 2 + 0] = (float)i1;
            out[t0 * 2 + 1] = (float)i2;
        }
    }
}

// ---------------------------------------------------------------------------
extern "C" void kernel_launch(void* const* d_in, const int* in_sizes, int n_in,
                              void* d_out, int out_size) {
    const float* x     = (const float*)d_in[0];
    const float* proto = (const float*)d_in[1];
    int ntok = in_sizes[2];                 // attn_mask element count = B*S
    if (ntok > MAXTOK) ntok = MAXTOK;
    float* out = (float*)d_out;

    norm_kernel<<<(ntok + 7) / 8, 256>>>(x, ntok);
    gemm_kernel<<<ntok / TM, NT>>>(x, proto);
    topk_kernel<<<(ntok + 7) / 8, 256>>>(out, ntok, out_size);
}

// round 2
// speedup vs baseline: 1.1248x; 1.1248x over previous
#include <cuda_runtime.h>
#include <math.h>

// x[8,2048,1024] fp32, prototypes[64,1024] fp32, attn_mask[8,2048] int32.
#define DDIM 1024
#define NEXP 64
#define SEQ  2048
#define TM   128
#define KC   64
#define NT   256
#define NCHUNK (DDIM / KC)
#define MAXTOK 16384

typedef unsigned long long u64;

__device__ float g_logits[MAXTOK * NEXP];   // normalized per-token logits

__device__ __forceinline__ u64 pack2(float lo, float hi) {
    u64 r; asm("mov.b64 %0, {%1, %2};" : "=l"(r) : "f"(lo), "f"(hi)); return r;
}
__device__ __forceinline__ void unpack2(u64 v, float& lo, float& hi) {
    asm("mov.b64 {%0, %1}, %2;" : "=f"(lo), "=f"(hi) : "l"(v));
}
__device__ __forceinline__ void fma2(u64& d, u64 a, u64 b) {
    asm("fma.rn.f32x2 %0, %1, %2, %3;" : "=l"(d) : "l"(a), "l"(b), "l"(d));
}

// ---------------------------------------------------------------------------
// Fused kernel: L[t,e] = (x_t . p_e) / max(||x_t||, 1e-8)
// Tile 128 tokens x 64 experts, K chunks of 64, 256 threads, 4x8 reg tile
// computed as 4x(4 f32x2). Per-row sum-of-squares fused from load registers.
// Register-prefetch pipeline hides DRAM latency (1 CTA/SM).
// ---------------------------------------------------------------------------
__global__ __launch_bounds__(NT) void gemm_kernel(const float* __restrict__ x,
                                                  const float* __restrict__ proto) {
    __shared__ float Asm[TM][KC + 4];      // [128][68]
    __shared__ float Psm[KC][NEXP + 4];    // [64][68] transposed, 16B-aligned rows
    __shared__ float partsq[TM][17];       // per-row sumsq partials (conflict-free)
    __shared__ float inorm_s[TM];

    const int t  = threadIdx.x;
    const int tx = t & 7;                  // experts tx*8 .. tx*8+7
    const int ty = t >> 3;                 // tokens ty*4 .. ty*4+3
    const int tb = t >> 4;                 // A-load row residue
    const int tc = t & 15;                 // A-load col group
    const size_t blockRow = (size_t)blockIdx.x * TM;

    u64 acc[4][4];
#pragma unroll
    for (int i = 0; i < 4; i++)
#pragma unroll
        for (int j = 0; j < 4; j++) acc[i][j] = 0ull;

    float srow[8];
#pragma unroll
    for (int i = 0; i < 8; i++) srow[i] = 0.f;

    float4 va[8], vp[4];

    // ---- load chunk 0 ----
#pragma unroll
    for (int i = 0; i < 8; i++)
        va[i] = *reinterpret_cast<const float4*>(
            x + (blockRow + tb + 16 * i) * DDIM + tc * 4);
#pragma unroll
    for (int i = 0; i < 4; i++) {
        int f = t + i * NT;
        vp[i] = *reinterpret_cast<const float4*>(
            proto + (size_t)(f >> 4) * DDIM + (f & 15) * 4);
    }
#pragma unroll
    for (int i = 0; i < 8; i++) {
        srow[i] += va[i].x * va[i].x + va[i].y * va[i].y +
                   va[i].z * va[i].z + va[i].w * va[i].w;
        *reinterpret_cast<float4*>(&Asm[tb + 16 * i][tc * 4]) = va[i];
    }
#pragma unroll
    for (int i = 0; i < 4; i++) {
        int f = t + i * NT, e = f >> 4, col = (f & 15) << 2;
        Psm[col + 0][e] = vp[i].x; Psm[col + 1][e] = vp[i].y;
        Psm[col + 2][e] = vp[i].z; Psm[col + 3][e] = vp[i].w;
    }
    __syncthreads();

    for (int c = 0; c < NCHUNK; c++) {
        // ---- prefetch chunk c+1 into registers ----
        if (c < NCHUNK - 1) {
            int kc = (c + 1) * KC;
#pragma unroll
            for (int i = 0; i < 8; i++)
                va[i] = *reinterpret_cast<const float4*>(
                    x + (blockRow + tb + 16 * i) * DDIM + kc + tc * 4);
#pragma unroll
            for (int i = 0; i < 4; i++) {
                int f = t + i * NT;
                vp[i] = *reinterpret_cast<const float4*>(
                    proto + (size_t)(f >> 4) * DDIM + kc + (f & 15) * 4);
            }
        }

        // ---- compute on chunk c ----
#pragma unroll 8
        for (int k = 0; k < KC; k++) {
            u64 ad[4];
#pragma unroll
            for (int i = 0; i < 4; i++) {
                float av = Asm[ty * 4 + i][k];
                ad[i] = pack2(av, av);
            }
            ulonglong2 q0 = *reinterpret_cast<const ulonglong2*>(&Psm[k][tx * 8]);
            ulonglong2 q1 = *reinterpret_cast<const ulonglong2*>(&Psm[k][tx * 8 + 4]);
#pragma unroll
            for (int i = 0; i < 4; i++) {
                fma2(acc[i][0], ad[i], q0.x);
                fma2(acc[i][1], ad[i], q0.y);
                fma2(acc[i][2], ad[i], q1.x);
                fma2(acc[i][3], ad[i], q1.y);
            }
        }
        __syncthreads();

        // ---- commit prefetched chunk to smem ----
        if (c < NCHUNK - 1) {
#pragma unroll
            for (int i = 0; i < 8; i++) {
                srow[i] += va[i].x * va[i].x + va[i].y * va[i].y +
                           va[i].z * va[i].z + va[i].w * va[i].w;
                *reinterpret_cast<float4*>(&Asm[tb + 16 * i][tc * 4]) = va[i];
            }
#pragma unroll
            for (int i = 0; i < 4; i++) {
                int f = t + i * NT, e = f >> 4, col = (f & 15) << 2;
                Psm[col + 0][e] = vp[i].x; Psm[col + 1][e] = vp[i].y;
                Psm[col + 2][e] = vp[i].z; Psm[col + 3][e] = vp[i].w;
            }
            __syncthreads();
        }
    }

    // ---- row-norm reduction (deterministic fixed order) ----
#pragma unroll
    for (int i = 0; i < 8; i++) partsq[tb + 16 * i][tc] = srow[i];
    __syncthreads();
    if (t < TM) {
        float s = 0.f;
#pragma unroll
        for (int c = 0; c < 16; c++) s += partsq[t][c];
        inorm_s[t] = 1.0f / fmaxf(sqrtf(s), 1e-8f);
    }
    __syncthreads();

    // ---- epilogue: scale & store logits ----
#pragma unroll
    for (int i = 0; i < 4; i++) {
        size_t row = blockRow + ty * 4 + i;
        float rn = inorm_s[ty * 4 + i];
        float o[8];
#pragma unroll
        for (int j = 0; j < 4; j++) {
            float lo, hi; unpack2(acc[i][j], lo, hi);
            o[2 * j] = lo * rn; o[2 * j + 1] = hi * rn;
        }
        *reinterpret_cast<float4*>(&g_logits[row * NEXP + tx * 8]) =
            make_float4(o[0], o[1], o[2], o[3]);
        *reinterpret_cast<float4*>(&g_logits[row * NEXP + tx * 8 + 4]) =
            make_float4(o[4], o[5], o[6], o[7]);
    }
}

// ---------------------------------------------------------------------------
// Kernel 2: window-3 average of logits, top-2 (tie -> lower index), renorm.
// ---------------------------------------------------------------------------
__device__ __forceinline__ bool better(float v, int vi, float w, int wi) {
    return (v > w) || (v == w && vi < wi);
}

__global__ void topk_kernel(float* __restrict__ out, int ntok, int out_size) {
    int warp = (blockIdx.x * blockDim.x + threadIdx.x) >> 5;
    int lane = threadIdx.x & 31;
    if (warp >= ntok) return;

    int b = warp / SEQ;
    int s = warp - b * SEQ;
    size_t t0 = (size_t)warp;
    size_t t1 = (size_t)b * SEQ + (s >= 1 ? s - 1 : 0);
    size_t t2 = (size_t)b * SEQ + (s >= 2 ? s - 2 : 0);

    float v0 = (g_logits[t0 * NEXP + lane] + g_logits[t1 * NEXP + lane] +
                g_logits[t2 * NEXP + lane]) / 3.0f;
    float v1 = (g_logits[t0 * NEXP + lane + 32] + g_logits[t1 * NEXP + lane + 32] +
                g_logits[t2 * NEXP + lane + 32]) / 3.0f;

    float a1, a2; int i1, i2;
    if (v0 >= v1) { a1 = v0; i1 = lane;      a2 = v1; i2 = lane + 32; }
    else          { a1 = v1; i1 = lane + 32; a2 = v0; i2 = lane;      }

#pragma unroll
    for (int off = 16; off; off >>= 1) {
        float ob1 = __shfl_xor_sync(0xffffffffu, a1, off);
        int   oj1 = __shfl_xor_sync(0xffffffffu, i1, off);
        float ob2 = __shfl_xor_sync(0xffffffffu, a2, off);
        int   oj2 = __shfl_xor_sync(0xffffffffu, i2, off);
        bool aw = better(a1, i1, ob1, oj1);
        float n1 = aw ? a1 : ob1;  int ni1 = aw ? i1 : oj1;
        float cc = aw ? ob1 : a1;  int ci  = aw ? oj1 : i1;
        float dd = aw ? a2 : ob2;  int di  = aw ? i2 : oj2;
        bool cw = better(cc, ci, dd, di);
        a1 = n1; i1 = ni1;
        a2 = cw ? cc : dd; i2 = cw ? ci : di;
    }

    if (lane == 0) {
        float e2 = expf(a2 - a1);
        float inv = 1.0f / (1.0f + e2);
        if (out_size >= 4 * ntok) {
            out[t0 * 2 + 0] = (float)i1;
            out[t0 * 2 + 1] = (float)i2;
            out[(size_t)ntok * 2 + t0 * 2 + 0] = inv;
            out[(size_t)ntok * 2 + t0 * 2 + 1] = e2 * inv;
        } else if (out_size >= 2 * ntok) {
            out[t0 * 2 + 0] = (float)i1;
            out[t0 * 2 + 1] = (float)i2;
        }
    }
}

// ---------------------------------------------------------------------------
extern "C" void kernel_launch(void* const* d_in, const int* in_sizes, int n_in,
                              void* d_out, int out_size) {
    const float* x     = (const float*)d_in[0];
    const float* proto = (const float*)d_in[1];
    int ntok = in_sizes[2];
    if (ntok > MAXTOK) ntok = MAXTOK;
    float* out = (float*)d_out;

    gemm_kernel<<<ntok / TM, NT>>>(x, proto);
    topk_kernel<<<(ntok + 7) / 8, 256>>>(out, ntok, out_size);
}

// round 5
// speedup vs baseline: 1.6125x; 1.4336x over previous
#include <cuda_runtime.h>
#include <math.h>

// x[8,2048,1024] fp32, prototypes[64,1024] fp32, attn_mask[8,2048] int32.
#define DDIM 1024
#define NEXP 64
#define SEQ  2048
#define TM   128
#define KC   64
#define KPAD 66          // smem row stride (floats): 2 mod 32 -> conflict-free
#define NT   256
#define NCHUNK (DDIM / KC)
#define MAXTOK 16384

typedef unsigned long long u64;

__device__ float g_logits[MAXTOK * NEXP];   // normalized per-token logits

__device__ __forceinline__ void unpack2(u64 v, float& lo, float& hi) {
    asm("mov.b64 {%0, %1}, %2;" : "=f"(lo), "=f"(hi) : "l"(v));
}
__device__ __forceinline__ void fma2(u64& d, u64 a, u64 b) {
    asm("fma.rn.f32x2 %0, %1, %2, %3;" : "=l"(d) : "l"(a), "l"(b), "l"(d));
}

// ---------------------------------------------------------------------------
// Fused kernel: L[t,e] = (x_t . p_e) / max(||x_t||, 1e-8)
// Tile 128 tokens x 64 experts. f32x2 FMA paired over K (even/odd k lanes),
// conflict-free LDS.64 operand reads, register-prefetch K pipeline,
// fused row sum-of-squares.
// ---------------------------------------------------------------------------
__global__ __launch_bounds__(NT, 1) void gemm_kernel(const float* __restrict__ x,
                                                     const float* __restrict__ proto) {
    __shared__ float Asm[TM * KPAD];       // [128][66] token-major
    __shared__ float Bsm[NEXP * KPAD];     // [64][66]  expert-major
    __shared__ float partsq[TM][17];
    __shared__ float inorm_s[TM];

    const int t  = threadIdx.x;
    const int tx = t & 7;                  // experts tx, tx+8, ..., tx+56
    const int ty = t >> 3;                 // tokens ty*4 .. ty*4+3
    const int tb = t >> 4;                 // A/B gmem load row residue
    const int tc = t & 15;                 // A/B gmem load col group
    const size_t blockRow = (size_t)blockIdx.x * TM;

    // Hoisted per-thread smem base pointers for the compute loop — leaves
    // only the +k immediate in the LDS addressing.
    const float* aBase = &Asm[(ty * 4) * KPAD];
    const float* bBase = &Bsm[tx * KPAD];

    u64 acc[4][8];                         // [row][expert], pair = (k even, k odd)
#pragma unroll
    for (int i = 0; i < 4; i++)
#pragma unroll
        for (int j = 0; j < 8; j++) acc[i][j] = 0ull;

    float srow[8];
#pragma unroll
    for (int i = 0; i < 8; i++) srow[i] = 0.f;

    float4 va[8], vp[4];

    // ---- stage chunk into smem (float2 stores: rows 8B- but not 16B-aligned)
    auto commitA = [&](int i) {
        float* d = &Asm[(tb + 16 * i) * KPAD + tc * 4];
        *reinterpret_cast<float2*>(d)     = make_float2(va[i].x, va[i].y);
        *reinterpret_cast<float2*>(d + 2) = make_float2(va[i].z, va[i].w);
        srow[i] += va[i].x * va[i].x + va[i].y * va[i].y +
                   va[i].z * va[i].z + va[i].w * va[i].w;
    };
    auto commitB = [&](int i) {
        int f = t + i * NT;                // 0..1023
        float* d = &Bsm[(f >> 4) * KPAD + (f & 15) * 4];
        *reinterpret_cast<float2*>(d)     = make_float2(vp[i].x, vp[i].y);
        *reinterpret_cast<float2*>(d + 2) = make_float2(vp[i].z, vp[i].w);
    };

    // ---- load chunk 0 ----
#pragma unroll
    for (int i = 0; i < 8; i++)
        va[i] = *reinterpret_cast<const float4*>(
            x + (blockRow + tb + 16 * i) * DDIM + tc * 4);
#pragma unroll
    for (int i = 0; i < 4; i++) {
        int f = t + i * NT;
        vp[i] = *reinterpret_cast<const float4*>(
            proto + (size_t)(f >> 4) * DDIM + (f & 15) * 4);
    }
#pragma unroll
    for (int i = 0; i < 8; i++) commitA(i);
#pragma unroll
    for (int i = 0; i < 4; i++) commitB(i);
    __syncthreads();

    for (int c = 0; c < NCHUNK; c++) {
        // ---- prefetch chunk c+1 into registers ----
        if (c < NCHUNK - 1) {
            int kc = (c + 1) * KC;
#pragma unroll
            for (int i = 0; i < 8; i++)
                va[i] = *reinterpret_cast<const float4*>(
                    x + (blockRow + tb + 16 * i) * DDIM + kc + tc * 4);
#pragma unroll
            for (int i = 0; i < 4; i++) {
                int f = t + i * NT;
                vp[i] = *reinterpret_cast<const float4*>(
                    proto + (size_t)(f >> 4) * DDIM + kc + (f & 15) * 4);
            }
        }

        // ---- compute chunk c: 32 k-pairs ----
#pragma unroll 8
        for (int k = 0; k < KC; k += 2) {
            u64 a2[4], b2[8];
#pragma unroll
            for (int i = 0; i < 4; i++)
                a2[i] = *reinterpret_cast<const u64*>(aBase + i * KPAD + k);
#pragma unroll
            for (int j = 0; j < 8; j++)
                b2[j] = *reinterpret_cast<const u64*>(bBase + j * (8 * KPAD) + k);
#pragma unroll
            for (int i = 0; i < 4; i++)
#pragma unroll
                for (int j = 0; j < 8; j++)
                    fma2(acc[i][j], a2[i], b2[j]);
        }
        __syncthreads();

        // ---- commit prefetched chunk ----
        if (c < NCHUNK - 1) {
#pragma unroll
            for (int i = 0; i < 8; i++) commitA(i);
#pragma unroll
            for (int i = 0; i < 4; i++) commitB(i);
            __syncthreads();
        }
    }

    // ---- row-norm reduction (deterministic fixed order) ----
#pragma unroll
    for (int i = 0; i < 8; i++) partsq[tb + 16 * i][tc] = srow[i];
    __syncthreads();
    if (t < TM) {
        float s = 0.f;
#pragma unroll
        for (int c2 = 0; c2 < 16; c2++) s += partsq[t][c2];
        inorm_s[t] = 1.0f / fmaxf(sqrtf(s), 1e-8f);
    }
    __syncthreads();

    // ---- epilogue: fold k-even/odd halves, scale, store ----
#pragma unroll
    for (int i = 0; i < 4; i++) {
        size_t row = blockRow + ty * 4 + i;
        float rn = inorm_s[ty * 4 + i];
#pragma unroll
        for (int j = 0; j < 8; j++) {
            float lo, hi; unpack2(acc[i][j], lo, hi);
            g_logits[row * NEXP + tx + 8 * j] = (lo + hi) * rn;
        }
    }
}

// ---------------------------------------------------------------------------
// Kernel 2: window-3 sum of logits (mean is monotone -> skip /3 for ranking),
// top-2 (tie -> lower index), renormalized weights.
// ---------------------------------------------------------------------------
__device__ __forceinline__ bool better(float v, int vi, float w, int wi) {
    return (v > w) || (v == w && vi < wi);
}

__global__ void topk_kernel(float* __restrict__ out, int ntok, int out_size) {
    int warp = (blockIdx.x * blockDim.x + threadIdx.x) >> 5;
    int lane = threadIdx.x & 31;
    if (warp >= ntok) return;

    int b = warp / SEQ;
    int s = warp - b * SEQ;
    size_t t0 = (size_t)warp;
    size_t t1 = (size_t)b * SEQ + (s >= 1 ? s - 1 : 0);
    size_t t2 = (size_t)b * SEQ + (s >= 2 ? s - 2 : 0);

    float v0 = g_logits[t0 * NEXP + lane] + g_logits[t1 * NEXP + lane] +
               g_logits[t2 * NEXP + lane];
    float v1 = g_logits[t0 * NEXP + lane + 32] + g_logits[t1 * NEXP + lane + 32] +
               g_logits[t2 * NEXP + lane + 32];

    float a1, a2; int i1, i2;
    if (v0 >= v1) { a1 = v0; i1 = lane;      a2 = v1; i2 = lane + 32; }
    else          { a1 = v1; i1 = lane + 32; a2 = v0; i2 = lane;      }

#pragma unroll
    for (int off = 16; off; off >>= 1) {
        float ob1 = __shfl_xor_sync(0xffffffffu, a1, off);
        int   oj1 = __shfl_xor_sync(0xffffffffu, i1, off);
        float ob2 = __shfl_xor_sync(0xffffffffu, a2, off);
        int   oj2 = __shfl_xor_sync(0xffffffffu, i2, off);
        bool aw = better(a1, i1, ob1, oj1);
        float n1 = aw ? a1 : ob1;  int ni1 = aw ? i1 : oj1;
        float cc = aw ? ob1 : a1;  int ci  = aw ? oj1 : i1;
        float dd = aw ? a2 : ob2;  int di  = aw ? i2 : oj2;
        bool cw = better(cc, ci, dd, di);
        a1 = n1; i1 = ni1;
        a2 = cw ? cc : dd; i2 = cw ? ci : di;
    }

    if (lane == 0) {
        // weights depend on the MEAN logit gap: (a2-a1)/3
        float e2 = expf((a2 - a1) * (1.0f / 3.0f));
        float inv = 1.0f / (1.0f + e2);
        if (out_size >= 4 * ntok) {
            out[t0 * 2 + 0] = (float)i1;
            out[t0 * 2 + 1] = (float)i2;
            out[(size_t)ntok * 2 + t0 * 2 + 0] = inv;
            out[(size_t)ntok * 2 + t0 * 2 + 1] = e2 * inv;
        } else if (out_size >= 2 * ntok) {
            out[t0 * 2 + 0] = (float)i1;
            out[t0 * 2 + 1] = (float)i2;
        }
    }
}

// ---------------------------------------------------------------------------
extern "C" void kernel_launch(void* const* d_in, const int* in_sizes, int n_in,
                              void* d_out, int out_size) {
    const float* x     = (const float*)d_in[0];
    const float* proto = (const float*)d_in[1];
    int ntok = in_sizes[2];
    if (ntok > MAXTOK) ntok = MAXTOK;
    float* out = (float*)d_out;

    gemm_kernel<<<ntok / TM, NT>>>(x, proto);
    topk_kernel<<<(ntok + 7) / 8, 256>>>(out, ntok, out_size);
}